// round 1
// baseline (speedup 1.0000x reference)
#include <cuda_runtime.h>

#define BB 32
#define SS 2048
#define II 128
#define HH 512
#define OO 64
#define NS 16384          // scan table resolution over tau in [0,4)
#define NO 2048           // readout table resolution
#define MAGICF 12582912.0f // 1.5 * 2^23 round-to-nearest magic

// ---------------- scratch (device globals; no allocation allowed) ----------
__device__ float  g_dot[BB*SS];
__device__ float2 g_mtau[BB*SS];                 // (m, idxf at NS scale) per (b,t)
__device__ float  g_G[NS+2];                     // scalar recurrence table
__device__ __align__(16) float g_Wt[HH*OO];      // W transposed [h][o]
__device__ __align__(16) float g_Gout[(NO+2)*OO];// readout tables [idx][o]
__device__ float  g_v[BB*SS*OO];                 // v_t[o] per (b,t)

// diamond (L1-sphere) parameter tau in [0,4) -> direction (S,C), |S|+|C|=1
__device__ __forceinline__ void tau_to_sc(float tau, float& Sv, float& Cv) {
    if (tau >= 4.0f) tau -= 4.0f;
    int q = (int)tau; if (q > 3) q = 3;
    float u = tau - (float)q;
    switch (q) {
        case 0:  Sv = 1.0f - u; Cv = u;        break;
        case 1:  Sv = -u;       Cv = 1.0f - u; break;
        case 2:  Sv = u - 1.0f; Cv = -u;       break;
        default: Sv = u;        Cv = u - 1.0f; break;
    }
}

// ---------------- K1: dot[b,t] = x[b,t,:] . input_receptive ---------------
__global__ void k_dot(const float* __restrict__ x, const float* __restrict__ ir) {
    int w    = (blockIdx.x * blockDim.x + threadIdx.x) >> 5;   // bt index
    int lane = threadIdx.x & 31;
    float4 xv  = ((const float4*)(x + (size_t)w * II))[lane];
    float4 irv = ((const float4*)ir)[lane];
    float p = xv.x*irv.x + xv.y*irv.y + xv.z*irv.z + xv.w*irv.w;
    #pragma unroll
    for (int o = 16; o; o >>= 1) p += __shfl_xor_sync(0xFFFFFFFFu, p, o);
    if (lane == 0) g_dot[w] = p;
}

// ---------------- K2: scan table G[k] = sum_h rr*relu(S*rp + C*ip) --------
__global__ void k_tab(const float* __restrict__ rp, const float* __restrict__ ipv,
                      const float* __restrict__ rr) {
    int k = blockIdx.x;                       // 0 .. NS+1
    float Sv, Cv; tau_to_sc(k * (4.0f / NS), Sv, Cv);
    int tid = threadIdx.x;                    // 64 threads
    float acc = 0.f;
    for (int h = tid; h < HH; h += 64)
        acc = fmaf(rr[h], fmaxf(fmaf(Sv, rp[h], Cv * ipv[h]), 0.f), acc);
    #pragma unroll
    for (int o = 16; o; o >>= 1) acc += __shfl_xor_sync(0xFFFFFFFFu, acc, o);
    __shared__ float red[2];
    if ((tid & 31) == 0) red[tid >> 5] = acc;
    __syncthreads();
    if (tid == 0) g_G[k] = red[0] + red[1];
}

// ---------------- K3: transpose W -> Wt[h][o] -----------------------------
__global__ void k_wt(const float* __restrict__ W) {
    int tid = blockIdx.x * blockDim.x + threadIdx.x;  // 32768
    int o = tid & 63, h = tid >> 6;
    g_Wt[tid] = W[o * HH + h];
}

// ---------------- K4: readout tables Gout[k][o] ---------------------------
__global__ void k_tab_out(const float* __restrict__ rp, const float* __restrict__ ipv) {
    __shared__ float su[4][520];              // padded: avoid bank conflicts
    int k0 = blockIdx.x * 4;
    int tid = threadIdx.x;                    // 64 threads
    #pragma unroll
    for (int kk = 0; kk < 4; ++kk) {
        int k = k0 + kk;
        if (k >= NO + 2) break;
        float Sv, Cv; tau_to_sc(k * (4.0f / NO), Sv, Cv);
        for (int h = tid; h < HH; h += 64)
            su[kk][h] = fmaxf(fmaf(Sv, rp[h], Cv * ipv[h]), 0.f);
    }
    __syncthreads();
    int kk = tid >> 4, og = tid & 15;
    int k = k0 + kk;
    if (k >= NO + 2) return;
    const float4* wt4 = (const float4*)g_Wt;
    float4 acc = make_float4(0.f, 0.f, 0.f, 0.f);
    #pragma unroll 8
    for (int h = 0; h < HH; ++h) {
        float u  = su[kk][h];
        float4 w = wt4[h * 16 + og];
        acc.x = fmaf(u, w.x, acc.x);
        acc.y = fmaf(u, w.y, acc.y);
        acc.z = fmaf(u, w.z, acc.z);
        acc.w = fmaf(u, w.w, acc.w);
    }
    ((float4*)(g_Gout + k * OO))[og] = acc;
}

// ---------------- K5: THE sequential scan (1 block per batch) -------------
// sigma' = 0.9*sigma + 0.1*m*G(tau);  stores (m, idxf) per step for readout.
#define SCAN_SMEM ((2*(NS+1) + SS) * 4)
__global__ void k_scan() {
    extern __shared__ float sm[];
    float2* spair = (float2*)sm;              // (G[i], G[i+1]) pairs, i<=NS
    float*  sdot  = sm + 2 * (NS + 1);        // this batch's dot stream
    int b = blockIdx.x, tid = threadIdx.x;
    for (int i = tid; i <= NS; i += blockDim.x)
        spair[i] = make_float2(g_G[i], g_G[i + 1]);
    for (int t = tid; t < SS; t += blockDim.x)
        sdot[t] = g_dot[b * SS + t];
    __syncthreads();
    if (tid == 0) {
        float s = 0.f;
        float2* out = g_mtau + b * SS;
        #pragma unroll 4
        for (int t = 0; t < SS; ++t) {
            float c  = sdot[t];
            float as = fabsf(s), ac = fabsf(c);
            float m  = as + ac;
            float mr = fmaxf(m, 1e-30f);
            float r;
            asm("rcp.approx.f32 %0, %1;" : "=f"(r) : "f"(mr));
            bool sp = (s >= 0.f), cp = (c >= 0.f);
            float w  = (sp != cp) ? as : ac;
            float b4 = sp ? (cp ? 0.f : 12288.f) : (cp ? 4096.f : 8192.f);
            float idxf = fmaf(w * r, 4096.f, b4);        // tau * NS/4
            float y  = idxf + MAGICF;
            int   i  = __float_as_int(y) & 0x7FFF;       // round-nearest index
            float fr = idxf - (y - MAGICF);              // signed frac in [-.5,.5]
            float2 gp = spair[i];
            float g  = fmaf(fr, gp.y - gp.x, gp.x);      // lerp
            out[t] = make_float2(m, idxf);
            s = fmaf(0.1f * m, g, 0.9f * s);
        }
    }
}

// ---------------- K6: v_t[o] = m * Gout(tau)[o]  (parallel over b,t) ------
__global__ void k_v() {
    int bt   = (blockIdx.x * blockDim.x + threadIdx.x) >> 5;
    int lane = threadIdx.x & 31;
    float2 mt = g_mtau[bt];
    float idxf = mt.y * ((float)NO / (float)NS);   // rescale to NO grid
    float y  = idxf + MAGICF;
    int   i  = __float_as_int(y) & 0xFFF;
    float fr = idxf - (y - MAGICF);
    const float* r0 = g_Gout + i * OO;
    float a0 = r0[lane],      a1 = r0[lane + 32];
    float b0 = r0[OO + lane], b1 = r0[OO + lane + 32];
    float v0 = mt.x * fmaf(fr, b0 - a0, a0);
    float v1 = mt.x * fmaf(fr, b1 - a1, a1);
    g_v[(size_t)bt * OO + lane]      = v0;
    g_v[(size_t)bt * OO + lane + 32] = v1;
}

// ---------------- K7: EMA over t + bias -> out ----------------------------
__global__ void k_out(float* __restrict__ out, const float* __restrict__ bias) {
    int w    = (blockIdx.x * blockDim.x + threadIdx.x) >> 5;  // 0..63
    int lane = threadIdx.x & 31;
    int b = w >> 1;
    int o = ((w & 1) << 5) + lane;
    float bv  = bias[o];
    const float* __restrict__ v = g_v + (size_t)b * SS * OO + o;
    float* __restrict__ op = out + (size_t)b * SS * OO + o;
    float acc = 0.f;
    #pragma unroll 16
    for (int t = 0; t < SS; ++t) {
        float vx = 0.1f * __ldg(&v[t * OO]);
        acc = fmaf(0.9f, acc, vx);
        op[t * OO] = acc + bv;
    }
}

// ---------------- launch ---------------------------------------------------
extern "C" void kernel_launch(void* const* d_in, const int* in_sizes, int n_in,
                              void* d_out, int out_size) {
    const float* x    = (const float*)d_in[0];
    const float* ip   = (const float*)d_in[1];  // input_projective [H]
    const float* ir   = (const float*)d_in[2];  // input_receptive [I]
    const float* rp   = (const float*)d_in[3];  // rec_projective [H]
    const float* rr   = (const float*)d_in[4];  // rec_receptive [H]
    const float* W    = (const float*)d_in[5];  // readout_w [O,H]
    const float* bias = (const float*)d_in[6];  // readout_b [O]
    float* out = (float*)d_out;

    k_dot<<<(BB*SS)/8, 256>>>(x, ir);
    k_tab<<<NS + 2, 64>>>(rp, ip, rr);
    k_wt<<<(HH*OO)/256, 256>>>(W);
    k_tab_out<<<(NO + 2 + 3) / 4, 64>>>(rp, ip);
    cudaFuncSetAttribute(k_scan, cudaFuncAttributeMaxDynamicSharedMemorySize, SCAN_SMEM);
    k_scan<<<BB, 128, SCAN_SMEM>>>();
    k_v<<<(BB*SS)/8, 256>>>();
    k_out<<<16, 128>>>(out, bias);
}

// round 2
// speedup vs baseline: 2.3471x; 2.3471x over previous
#include <cuda_runtime.h>

#define BB 32
#define SS 2048
#define II 128
#define HH 512
#define OO 64
#define N4 32768            // scan table: tau in [0,4], nearest-neighbor
#define KSC 8192.0f         // N4/4
#define NO 2048             // readout table: tau in [0,4], nearest-neighbor
#define MAGICF 12582912.0f  // 1.5*2^23
#define MAGICI 1262485504   // 0x4B400000

// ---------------- scratch ----------------
__device__ float  g_dot[BB*SS];
__device__ float2 g_mtau[BB*SS];                    // (m, idxf scan-scale)
__device__ __align__(16) float g_G4[N4+260];        // scalar recurrence table
__device__ __align__(16) float g_Wt[HH*OO];         // W transposed [h][o]
__device__ __align__(16) float g_Gout[(NO+8)*OO];   // readout tables

// tau in [0,4) -> diamond direction (S,C), |S|+|C|=1 (continuous)
__device__ __forceinline__ void tau_to_sc(float tau, float& Sv, float& Cv) {
    if (tau >= 4.0f) tau -= 4.0f;
    int q = (int)tau; if (q > 3) q = 3;
    float u = tau - (float)q;
    switch (q) {
        case 0:  Sv = 1.0f - u; Cv = u;        break;
        case 1:  Sv = -u;       Cv = 1.0f - u; break;
        case 2:  Sv = u - 1.0f; Cv = -u;       break;
        default: Sv = u;        Cv = u - 1.0f; break;
    }
}

// ---------------- K1: dot[b,t] = x[b,t,:] . input_receptive ---------------
__global__ void k_dot(const float* __restrict__ x, const float* __restrict__ ir) {
    int w    = (blockIdx.x * blockDim.x + threadIdx.x) >> 5;
    int lane = threadIdx.x & 31;
    float4 xv  = ((const float4*)(x + (size_t)w * II))[lane];
    float4 irv = ((const float4*)ir)[lane];
    float p = xv.x*irv.x + xv.y*irv.y + xv.z*irv.z + xv.w*irv.w;
    #pragma unroll
    for (int o = 16; o; o >>= 1) p += __shfl_xor_sync(0xFFFFFFFFu, p, o);
    if (lane == 0) g_dot[w] = p;
}

// ---------------- K2: scan table (one k per thread, params in smem) -------
__global__ void k_tab(const float* __restrict__ rp, const float* __restrict__ ipv,
                      const float* __restrict__ rr) {
    __shared__ float srp[HH], sip[HH], srr[HH];
    int tid = threadIdx.x;
    for (int h = tid; h < HH; h += 256) { srp[h] = rp[h]; sip[h] = ipv[h]; srr[h] = rr[h]; }
    __syncthreads();
    int k = blockIdx.x * 256 + tid;
    float Sv, Cv; tau_to_sc((float)k * (4.0f / N4), Sv, Cv);
    float acc = 0.f;
    #pragma unroll 4
    for (int h = 0; h < HH; ++h)
        acc = fmaf(srr[h], fmaxf(fmaf(Sv, srp[h], Cv * sip[h]), 0.f), acc);
    g_G4[k] = acc;
}

// ---------------- K3: transpose W (coalesced read) ------------------------
__global__ void k_wt(const float* __restrict__ W) {
    int tid = blockIdx.x * blockDim.x + threadIdx.x;  // 32768
    int o = tid >> 9, h = tid & 511;
    g_Wt[h * OO + o] = W[tid];
}

// ---------------- K4: readout tables, Wt staged in smem -------------------
#define TABOUT_SMEM ((HH*OO + 8*HH) * 4)
__global__ void k_tab_out(const float* __restrict__ rp, const float* __restrict__ ipv) {
    extern __shared__ float sm[];
    float* Wsm = sm;               // [512][64]
    float* u   = sm + HH * OO;     // [8][512]
    int tid = threadIdx.x;         // 256
    const float4* src = (const float4*)g_Wt;
    float4* dst = (float4*)Wsm;
    for (int i = tid; i < HH * OO / 4; i += 256) dst[i] = src[i];
    int w = tid >> 5, lane = tid & 31;
    {
        int k = blockIdx.x * 8 + w;
        float Sv, Cv; tau_to_sc((float)k * (4.0f / NO), Sv, Cv);
        for (int h = lane; h < HH; h += 32)
            u[w * HH + h] = fmaxf(fmaf(Sv, rp[h], Cv * ipv[h]), 0.f);
    }
    __syncthreads();
    int o = tid & 63, kg = tid >> 6;      // kg in 0..3, handles kg and kg+4
    float a0 = 0.f, a1 = 0.f;
    #pragma unroll 4
    for (int h = 0; h < HH; ++h) {
        float wv = Wsm[h * OO + o];
        a0 = fmaf(u[kg * HH + h],       wv, a0);
        a1 = fmaf(u[(kg + 4) * HH + h], wv, a1);
    }
    int k0 = blockIdx.x * 8;
    g_Gout[(k0 + kg) * OO + o]     = a0;
    g_Gout[(k0 + kg + 4) * OO + o] = a1;
}

// ---------------- K5: sequential scan, shortened chain --------------------
// tau = qa + qs*u with u = |c|/m always; nearest lookup; idxf = tau*8192.
#define SCAN_SMEM ((N4 + 4 + SS) * 4)
__global__ void k_scan() {
    extern __shared__ float sm[];
    float* tab  = sm;               // N4+1 entries (staged as float4)
    float* sdot = sm + (N4 + 4);
    int b = blockIdx.x, tid = threadIdx.x;   // 256 threads
    const float4* g4 = (const float4*)g_G4;
    float4* t4 = (float4*)tab;
    for (int i = tid; i < (N4 + 4) / 4; i += 256) t4[i] = g4[i];
    for (int t = tid; t < SS; t += 256) sdot[t] = g_dot[b * SS + t];
    __syncthreads();
    if (tid == 0) {
        float s = 0.f;
        float2* out = g_mtau + b * SS;
        #pragma unroll 4
        for (int t = 0; t < SS; ++t) {
            // ---- c-side precompute (independent of s, off critical path) ----
            float c   = sdot[t];
            float ac  = fabsf(c);
            float Kac = KSC * ac;
            float Ap, An, Bp;
            if (c >= 0.f) { Ap =  Kac; An = -Kac; Bp = 0.f; }
            else          { Ap = -Kac; An =  Kac; Bp = 32768.f; }
            // ---- critical chain ----
            float m = fabsf(s) + ac;                       // FADD.|.|
            float r; asm("rcp.approx.f32 %0, %1;" : "=f"(r) : "f"(m));
            bool sp = (s >= 0.f);
            float aqs = sp ? Ap : An;                      // FSETP+FSEL, off-chain
            float qaK = sp ? Bp : 16384.f;
            float idxf = fmaf(aqs, r, qaK);                // tau * 8192
            idxf = fminf(idxf, 32768.f);                   // NaN (m=0) safe
            float y  = idxf + MAGICF;
            int   ib = __float_as_int(y) - MAGICI;         // round-nearest idx
            float g  = tab[ib];
            out[t] = make_float2(m, idxf);                 // STG.64 off-chain
            s = fmaf(g, 0.1f * m, 0.9f * s);
        }
    }
}

// ---------------- K6: fused readout lookup + EMA + bias -------------------
// 0.9^128 = 1.4e-6: each 128-step output chunk warm-started 128 steps back.
__global__ void k_vo(float* __restrict__ out, const float* __restrict__ bias) {
    __shared__ float2 smt[256];
    int b  = blockIdx.x >> 4;
    int ch = blockIdx.x & 15;
    int t0 = ch * 128;
    int tw = (ch == 0) ? 0 : t0 - 128;
    int nt = t0 + 128 - tw;
    int tid = threadIdx.x;          // 64, one per o
    for (int i = tid; i < nt; i += 64) smt[i] = g_mtau[b * SS + tw + i];
    __syncthreads();
    float bv = bias[tid];
    float acc = 0.f;
    int nwarm = t0 - tw;
    #pragma unroll 4
    for (int i = 0; i < nwarm; ++i) {
        float2 mt = smt[i];
        float yf = fmaf(mt.y, 0.0625f, MAGICF);      // /16: scan grid -> NO grid
        int idx = __float_as_int(yf) - MAGICI;
        float g = g_Gout[idx * OO + tid];
        acc = fmaf(0.9f, acc, g * (0.1f * mt.x));
    }
    float* op = out + ((size_t)b * SS + t0) * OO + tid;
    #pragma unroll 4
    for (int j = 0; j < 128; ++j) {
        float2 mt = smt[nwarm + j];
        float yf = fmaf(mt.y, 0.0625f, MAGICF);
        int idx = __float_as_int(yf) - MAGICI;
        float g = g_Gout[idx * OO + tid];
        acc = fmaf(0.9f, acc, g * (0.1f * mt.x));
        op[j * OO] = acc + bv;
    }
}

// ---------------- launch ---------------------------------------------------
extern "C" void kernel_launch(void* const* d_in, const int* in_sizes, int n_in,
                              void* d_out, int out_size) {
    const float* x    = (const float*)d_in[0];
    const float* ip   = (const float*)d_in[1];
    const float* ir   = (const float*)d_in[2];
    const float* rp   = (const float*)d_in[3];
    const float* rr   = (const float*)d_in[4];
    const float* W    = (const float*)d_in[5];
    const float* bias = (const float*)d_in[6];
    float* out = (float*)d_out;

    cudaFuncSetAttribute(k_scan,    cudaFuncAttributeMaxDynamicSharedMemorySize, SCAN_SMEM);
    cudaFuncSetAttribute(k_tab_out, cudaFuncAttributeMaxDynamicSharedMemorySize, TABOUT_SMEM);

    k_dot<<<(BB*SS)/8, 256>>>(x, ir);
    k_tab<<<(N4/256) + 1, 256>>>(rp, ip, rr);            // 129 blocks
    k_wt<<<(HH*OO)/256, 256>>>(W);
    k_tab_out<<<(NO + 8)/8, 256, TABOUT_SMEM>>>(rp, ip); // 257 blocks
    k_scan<<<BB, 256, SCAN_SMEM>>>();
    k_vo<<<BB*16, 64>>>(out, bias);
}

// round 3
// speedup vs baseline: 3.3687x; 1.4353x over previous
#include <cuda_runtime.h>

#define BB 32
#define SS 2048
#define II 128
#define HH 512
#define OO 64
#define N4 32768            // scan table: tau in [0,4], nearest-neighbor
#define KSC 8192.0f         // N4/4
#define NO 2048             // readout table grid
#define MAGICF 12582912.0f  // 1.5*2^23
#define MAGICI 1262485504   // bits of MAGICF
#define LCH 16              // scan chunk length per thread
#define NSWEEP 12           // waveform-relaxation sweeps (gamma^192 ~ 2e-8)

// ---------------- scratch ----------------
__device__ float  g_dot[BB*SS];
__device__ float2 g_mtau[BB*SS];                    // (m, int_bits(ib))
__device__ __align__(16) float g_G4[N4+260];        // scalar recurrence table
__device__ __align__(16) float g_Wt[HH*OO];         // W transposed [h][o]
__device__ __align__(16) float g_Gout[(NO+32)*OO];  // readout tables

// tau in [0,4) -> diamond direction (S,C), |S|+|C|=1
__device__ __forceinline__ void tau_to_sc(float tau, float& Sv, float& Cv) {
    if (tau >= 4.0f) tau -= 4.0f;
    int q = (int)tau; if (q > 3) q = 3;
    float u = tau - (float)q;
    switch (q) {
        case 0:  Sv = 1.0f - u; Cv = u;        break;
        case 1:  Sv = -u;       Cv = 1.0f - u; break;
        case 2:  Sv = u - 1.0f; Cv = -u;       break;
        default: Sv = u;        Cv = u - 1.0f; break;
    }
}

// one recurrence step; magic-folded rounding, no clamps on the chain
__device__ __forceinline__ void scan_step(float c, float& s, const float* __restrict__ tab,
                                          float& m_out, int& ib_out) {
    float ac  = fabsf(c) + 1e-35f;           // m>0 guard, off-chain
    float Kac = KSC * ac;
    float Ap, An, BpM;
    if (c >= 0.f) { Ap =  Kac; An = -Kac; BpM = MAGICF; }
    else          { Ap = -Kac; An =  Kac; BpM = MAGICF + 32768.f; }
    float m = fabsf(s) + ac;                               // FADD |.|
    float r; asm("rcp.approx.f32 %0, %1;" : "=f"(r) : "f"(m)); // MUFU 16
    bool sp = (s >= 0.f);
    float aqs = sp ? Ap  : An;                             // off-chain sel
    float qaK = sp ? BpM : (MAGICF + 16384.f);
    float y  = fmaf(aqs, r, qaK);                          // rounds to int (ulp=1)
    int   ib = __float_as_int(y) - MAGICI;                 // 0..32768
    float g  = tab[ib];                                    // LDS
    m_out = m; ib_out = ib;
    s = fmaf(g, 0.1f * m, 0.9f * s);                       // FFMA
}

// ---------------- K1: dot[b,t] = x[b,t,:] . input_receptive ---------------
__global__ void k_dot(const float* __restrict__ x, const float* __restrict__ ir) {
    int w    = (blockIdx.x * blockDim.x + threadIdx.x) >> 5;
    int lane = threadIdx.x & 31;
    float4 xv  = ((const float4*)(x + (size_t)w * II))[lane];
    float4 irv = ((const float4*)ir)[lane];
    float p = xv.x*irv.x + xv.y*irv.y + xv.z*irv.z + xv.w*irv.w;
    #pragma unroll
    for (int o = 16; o; o >>= 1) p += __shfl_xor_sync(0xFFFFFFFFu, p, o);
    if (lane == 0) g_dot[w] = p;
}

// ---------------- K2: scan table --------------------------------------
__global__ void k_tab(const float* __restrict__ rp, const float* __restrict__ ipv,
                      const float* __restrict__ rr) {
    __shared__ float srp[HH], sip[HH], srr[HH];
    int tid = threadIdx.x;
    for (int h = tid; h < HH; h += 256) { srp[h] = rp[h]; sip[h] = ipv[h]; srr[h] = rr[h]; }
    __syncthreads();
    int k = blockIdx.x * 256 + tid;
    float Sv, Cv; tau_to_sc((float)k * (4.0f / N4), Sv, Cv);
    float acc = 0.f;
    #pragma unroll 4
    for (int h = 0; h < HH; ++h)
        acc = fmaf(srr[h], fmaxf(fmaf(Sv, srp[h], Cv * sip[h]), 0.f), acc);
    g_G4[k] = acc;
}

// ---------------- K3: transpose W -----------------------------------------
__global__ void k_wt(const float* __restrict__ W) {
    int tid = blockIdx.x * blockDim.x + threadIdx.x;  // 32768
    int o = tid >> 9, h = tid & 511;
    g_Wt[h * OO + o] = W[tid];
}

// ---------------- K4: readout tables (2k x 4o register tile) --------------
__global__ void k_tab_out(const float* __restrict__ rp, const float* __restrict__ ipv) {
    __shared__ float su[16 * HH];             // su[h*16 + k], 32KB
    int tid = threadIdx.x;                    // 128
    {
        int k = tid & 15;
        float Sv, Cv; tau_to_sc((float)(blockIdx.x * 16 + k) * (4.0f / NO), Sv, Cv);
        for (int h = tid >> 4; h < HH; h += 8)
            su[h * 16 + k] = fmaxf(fmaf(Sv, rp[h], Cv * ipv[h]), 0.f);
    }
    __syncthreads();
    int o4 = tid & 15, k2 = tid >> 4;         // k2 in 0..7 -> k = 2k2, 2k2+1
    const float4* wt4 = (const float4*)g_Wt;
    const float2* su2 = (const float2*)su;
    float4 a0 = make_float4(0,0,0,0), a1 = make_float4(0,0,0,0);
    #pragma unroll 4
    for (int h = 0; h < HH; ++h) {
        float4 w  = __ldg(&wt4[h * 16 + o4]);
        float2 uu = su2[h * 8 + k2];
        a0.x = fmaf(uu.x, w.x, a0.x); a0.y = fmaf(uu.x, w.y, a0.y);
        a0.z = fmaf(uu.x, w.z, a0.z); a0.w = fmaf(uu.x, w.w, a0.w);
        a1.x = fmaf(uu.y, w.x, a1.x); a1.y = fmaf(uu.y, w.y, a1.y);
        a1.z = fmaf(uu.y, w.z, a1.z); a1.w = fmaf(uu.y, w.w, a1.w);
    }
    int row = blockIdx.x * 16 + 2 * k2;
    ((float4*)(g_Gout + (size_t)row * OO))[o4]       = a0;
    ((float4*)(g_Gout + (size_t)(row + 1) * OO))[o4] = a1;
}

// ---------------- K5: waveform-relaxation scan ----------------------------
// 128 threads x 16-step chunks; NSWEEP Jacobi-across/Seidel-within sweeps.
#define SCAN_SMEM (((N4 + 4) + SS + 132) * 4)
__global__ void k_scan() {
    extern __shared__ float sm[];
    float* tab    = sm;                        // N4+4
    float* sdot   = sm + (N4 + 4);             // SS
    float* sbound = sdot + SS;                 // 129 chunk boundary values
    int b = blockIdx.x, tid = threadIdx.x;     // 256 threads
    const float4* g4 = (const float4*)g_G4;
    float4* t4 = (float4*)tab;
    for (int i = tid; i < (N4 + 4) / 4; i += 256) t4[i] = g4[i];
    for (int t = tid; t < SS; t += 256) sdot[t] = g_dot[b * SS + t];
    if (tid < 132) sbound[tid] = 0.f;
    __syncthreads();

    float mo; int ibo;
    for (int sw = 0; sw < NSWEEP; ++sw) {
        float s = (tid < 128) ? sbound[tid] : 0.f;
        __syncthreads();
        if (tid < 128) {
            const float* cd = sdot + tid * LCH;
            #pragma unroll
            for (int j = 0; j < LCH; ++j) scan_step(cd[j], s, tab, mo, ibo);
            sbound[tid + 1] = s;
        }
        __syncthreads();
    }
    // final sweep: recompute with converged boundaries, emit (m, ib)
    if (tid < 128) {
        float s = sbound[tid];
        const float* cd = sdot + tid * LCH;
        float2* out = g_mtau + b * SS + tid * LCH;
        #pragma unroll
        for (int j = 0; j < LCH; ++j) {
            scan_step(cd[j], s, tab, mo, ibo);
            out[j] = make_float2(mo, __int_as_float(ibo));
        }
    }
}

// ---------------- K6: fused readout lookup + EMA + bias -------------------
__global__ void k_vo(float* __restrict__ out, const float* __restrict__ bias) {
    __shared__ float2 smt[256];
    int b  = blockIdx.x >> 4;
    int ch = blockIdx.x & 15;
    int t0 = ch * 128;
    int tw = (ch == 0) ? 0 : t0 - 128;
    int nt = t0 + 128 - tw;
    int tid = threadIdx.x;          // 64, one per o
    for (int i = tid; i < nt; i += 64) smt[i] = g_mtau[b * SS + tw + i];
    __syncthreads();
    float bv = bias[tid];
    float acc = 0.f;
    int nwarm = t0 - tw;
    #pragma unroll 4
    for (int i = 0; i < nwarm; ++i) {
        float2 mt = smt[i];
        int idx = (__float_as_int(mt.y) + 8) >> 4;
        float g = g_Gout[(size_t)idx * OO + tid];
        acc = fmaf(0.9f, acc, g * (0.1f * mt.x));
    }
    float* op = out + ((size_t)b * SS + t0) * OO + tid;
    #pragma unroll 4
    for (int j = 0; j < 128; ++j) {
        float2 mt = smt[nwarm + j];
        int idx = (__float_as_int(mt.y) + 8) >> 4;
        float g = g_Gout[(size_t)idx * OO + tid];
        acc = fmaf(0.9f, acc, g * (0.1f * mt.x));
        op[j * OO] = acc + bv;
    }
}

// ---------------- launch ---------------------------------------------------
extern "C" void kernel_launch(void* const* d_in, const int* in_sizes, int n_in,
                              void* d_out, int out_size) {
    const float* x    = (const float*)d_in[0];
    const float* ip   = (const float*)d_in[1];
    const float* ir   = (const float*)d_in[2];
    const float* rp   = (const float*)d_in[3];
    const float* rr   = (const float*)d_in[4];
    const float* W    = (const float*)d_in[5];
    const float* bias = (const float*)d_in[6];
    float* out = (float*)d_out;

    cudaFuncSetAttribute(k_scan, cudaFuncAttributeMaxDynamicSharedMemorySize, SCAN_SMEM);

    k_dot<<<(BB*SS)/8, 256>>>(x, ir);
    k_tab<<<(N4/256) + 1, 256>>>(rp, ip, rr);         // covers 0..33023
    k_wt<<<(HH*OO)/256, 256>>>(W);
    k_tab_out<<<(NO + 32)/16, 128>>>(rp, ip);         // 130 blocks -> rows 0..2079
    k_scan<<<BB, 256, SCAN_SMEM>>>();
    k_vo<<<BB*16, 64>>>(out, bias);
}

// round 4
// speedup vs baseline: 7.0841x; 2.1029x over previous
#include <cuda_runtime.h>

#define BB 32
#define SS 2048
#define II 128
#define HH 512
#define OO 64
#define N4 32768            // scan table: tau in [0,4], nearest-neighbor
#define KSC 8192.0f         // N4/4
#define NO 2048             // readout table grid
#define MAGICF 12582912.0f  // 1.5*2^23
#define MAGICI 1262485504   // bits of MAGICF
#define LCH 16              // scan chunk length per thread
#define NSWEEP 8            // waveform sweeps: gamma^128 ~ 1e-5 residual

// ---------------- scratch ----------------
__device__ float  g_dot[BB*SS];
__device__ float2 g_mtau[BB*SS];                    // (m, int_bits(ib))
__device__ __align__(16) float g_G4[N4+260];        // scalar recurrence table
__device__ __align__(16) float g_Gout[2112*OO];     // readout tables (33*64 rows)

// tau in [0,4) -> diamond direction (S,C), |S|+|C|=1
__device__ __forceinline__ void tau_to_sc(float tau, float& Sv, float& Cv) {
    if (tau >= 4.0f) tau -= 4.0f;
    int q = (int)tau; if (q > 3) q = 3;
    float u = tau - (float)q;
    switch (q) {
        case 0:  Sv = 1.0f - u; Cv = u;        break;
        case 1:  Sv = -u;       Cv = 1.0f - u; break;
        case 2:  Sv = u - 1.0f; Cv = -u;       break;
        default: Sv = u;        Cv = u - 1.0f; break;
    }
}

// one recurrence step; magic-folded rounding, minimal critical chain
__device__ __forceinline__ void scan_step(float c, float& s, const float* __restrict__ tab,
                                          float& m_out, int& ib_out) {
    float ac  = fabsf(c) + 1e-35f;
    float Kac = KSC * ac;
    float Ap, An, BpM;
    if (c >= 0.f) { Ap =  Kac; An = -Kac; BpM = MAGICF; }
    else          { Ap = -Kac; An =  Kac; BpM = MAGICF + 32768.f; }
    float m = fabsf(s) + ac;
    float r; asm("rcp.approx.f32 %0, %1;" : "=f"(r) : "f"(m));
    bool sp = (s >= 0.f);
    float aqs = sp ? Ap  : An;
    float qaK = sp ? BpM : (MAGICF + 16384.f);
    float y  = fmaf(aqs, r, qaK);          // FMA rounds to integer grid (ulp=1)
    int   ib = __float_as_int(y) - MAGICI; // 0..32768
    float g  = tab[ib];
    m_out = m; ib_out = ib;
    s = fmaf(g, 0.1f * m, 0.9f * s);
}

// ---------------- K1: dot[b,t] = x[b,t,:] . input_receptive ---------------
__global__ void k_dot(const float* __restrict__ x, const float* __restrict__ ir) {
    int w    = (blockIdx.x * blockDim.x + threadIdx.x) >> 5;
    int lane = threadIdx.x & 31;
    float4 xv  = ((const float4*)(x + (size_t)w * II))[lane];
    float4 irv = ((const float4*)ir)[lane];
    float p = xv.x*irv.x + xv.y*irv.y + xv.z*irv.z + xv.w*irv.w;
    #pragma unroll
    for (int o = 16; o; o >>= 1) p += __shfl_xor_sync(0xFFFFFFFFu, p, o);
    if (lane == 0) g_dot[w] = p;
}

// ---------------- K2: scan table ------------------------------------------
__global__ void k_tab(const float* __restrict__ rp, const float* __restrict__ ipv,
                      const float* __restrict__ rr) {
    __shared__ float srp[HH], sip[HH], srr[HH];
    int tid = threadIdx.x;
    for (int h = tid; h < HH; h += 256) { srp[h] = rp[h]; sip[h] = ipv[h]; srr[h] = rr[h]; }
    __syncthreads();
    int k = blockIdx.x * 256 + tid;
    float Sv, Cv; tau_to_sc((float)k * (4.0f / N4), Sv, Cv);
    float acc = 0.f;
    #pragma unroll 4
    for (int h = 0; h < HH; ++h)
        acc = fmaf(srr[h], fmaxf(fmaf(Sv, srp[h], Cv * sip[h]), 0.f), acc);
    g_G4[k] = acc;
}

// ---------------- K3: readout tables — smem tiled GEMM --------------------
// grid (33, 4): block = 64 k-rows x 16 o-cols. 128 threads.
// smem: Wsm[512][18] (o-tile, padded) + su[512][64] (u values) + rp/ip stage.
#define WPAD 18
#define TOB_SMEM ((HH*WPAD + HH*64 + 2*HH) * 4)
__global__ void k_tab_out(const float* __restrict__ W, const float* __restrict__ rp,
                          const float* __restrict__ ipv) {
    extern __shared__ float sm[];
    float* Wsm = sm;                    // [h][16] padded to 18
    float* su  = sm + HH * WPAD;        // [h][64]
    float* srp = su + HH * 64;          // [512]
    float* sip = srp + HH;              // [512]
    int tid = threadIdx.x;              // 128
    int o0  = blockIdx.y * 16;
    int k0  = blockIdx.x * 64;

    // stage rp/ip
    {
        const float4* rp4 = (const float4*)rp;
        const float4* ip4 = (const float4*)ipv;
        ((float4*)srp)[tid] = rp4[tid];
        ((float4*)sip)[tid] = ip4[tid];
    }
    // stage W o-tile transposed: Wsm[h][og]
    {
        int og = tid >> 4, hl = tid & 15;          // og 0..7 -> handles og, og+8
        #pragma unroll
        for (int g2 = 0; g2 < 2; ++g2) {
            int o = og + g2 * 8;
            const float4* wr = (const float4*)(W + (size_t)(o0 + o) * HH);
            #pragma unroll
            for (int i = 0; i < 8; ++i) {
                float4 wv = wr[hl + i * 16];
                int h = (hl + i * 16) * 4;
                Wsm[(h + 0) * WPAD + o] = wv.x;
                Wsm[(h + 1) * WPAD + o] = wv.y;
                Wsm[(h + 2) * WPAD + o] = wv.z;
                Wsm[(h + 3) * WPAD + o] = wv.w;
            }
        }
    }
    __syncthreads();
    // compute u[h][k] for this block's 64 k-rows
    {
        int k = tid & 63, hp = tid >> 6;           // 2 h-phases
        float Sv, Cv; tau_to_sc((float)(k0 + k) * (4.0f / NO), Sv, Cv);
        #pragma unroll 4
        for (int h = hp; h < HH; h += 2)
            su[h * 64 + k] = fmaxf(fmaf(Sv, srp[h], Cv * sip[h]), 0.f);
    }
    __syncthreads();
    // GEMM: thread = (kg 0..15, oq 0..7): 4k x 2o register tile
    int kg = tid & 15, oq = tid >> 4;
    float4 a0 = make_float4(0,0,0,0), a1 = make_float4(0,0,0,0);
    #pragma unroll 4
    for (int h = 0; h < HH; ++h) {
        float4 u4 = *(const float4*)&su[h * 64 + 4 * kg];
        float2 w2 = *(const float2*)&Wsm[h * WPAD + 2 * oq];
        a0.x = fmaf(u4.x, w2.x, a0.x); a1.x = fmaf(u4.x, w2.y, a1.x);
        a0.y = fmaf(u4.y, w2.x, a0.y); a1.y = fmaf(u4.y, w2.y, a1.y);
        a0.z = fmaf(u4.z, w2.x, a0.z); a1.z = fmaf(u4.z, w2.y, a1.z);
        a0.w = fmaf(u4.w, w2.x, a0.w); a1.w = fmaf(u4.w, w2.y, a1.w);
    }
    int row = k0 + 4 * kg, oc = o0 + 2 * oq;
    float* gp = g_Gout + (size_t)row * OO + oc;
    gp[0*OO+0]=a0.x; gp[0*OO+1]=a1.x;
    gp[1*OO+0]=a0.y; gp[1*OO+1]=a1.y;
    gp[2*OO+0]=a0.z; gp[2*OO+1]=a1.z;
    gp[3*OO+0]=a0.w; gp[3*OO+1]=a1.w;
}

// ---------------- K4: waveform-relaxation scan ----------------------------
#define SCAN_SMEM (((N4 + 4) + SS + 132) * 4)
__global__ void k_scan() {
    extern __shared__ float sm[];
    float* tab    = sm;
    float* sdot   = sm + (N4 + 4);
    float* sbound = sdot + SS;
    int b = blockIdx.x, tid = threadIdx.x;     // 256 threads
    const float4* g4 = (const float4*)g_G4;
    float4* t4 = (float4*)tab;
    for (int i = tid; i < (N4 + 4) / 4; i += 256) t4[i] = g4[i];
    for (int t = tid; t < SS; t += 256) sdot[t] = g_dot[b * SS + t];
    if (tid < 132) sbound[tid] = 0.f;
    __syncthreads();

    float mo; int ibo;
    for (int sw = 0; sw < NSWEEP; ++sw) {
        float s = (tid < 128) ? sbound[tid] : 0.f;
        __syncthreads();
        if (tid < 128) {
            const float* cd = sdot + tid * LCH;
            #pragma unroll
            for (int j = 0; j < LCH; ++j) scan_step(cd[j], s, tab, mo, ibo);
            sbound[tid + 1] = s;
        }
        __syncthreads();
    }
    if (tid < 128) {
        float s = sbound[tid];
        const float* cd = sdot + tid * LCH;
        float2* out = g_mtau + b * SS + tid * LCH;
        #pragma unroll
        for (int j = 0; j < LCH; ++j) {
            scan_step(cd[j], s, tab, mo, ibo);
            out[j] = make_float2(mo, __int_as_float(ibo));
        }
    }
}

// ---------------- K5: fused readout lookup + EMA + bias -------------------
__global__ void k_vo(float* __restrict__ out, const float* __restrict__ bias) {
    __shared__ float2 smt[256];
    int b  = blockIdx.x >> 4;
    int ch = blockIdx.x & 15;
    int t0 = ch * 128;
    int tw = (ch == 0) ? 0 : t0 - 128;
    int nt = t0 + 128 - tw;
    int tid = threadIdx.x;          // 64, one per o
    for (int i = tid; i < nt; i += 64) smt[i] = g_mtau[b * SS + tw + i];
    __syncthreads();
    float bv = bias[tid];
    float acc = 0.f;
    int nwarm = t0 - tw;            // 0 or 128
    for (int jb = 0; jb < nwarm; jb += 16) {
        float gv[16], mm[16];
        #pragma unroll
        for (int q = 0; q < 16; ++q) {
            float2 mt = smt[jb + q];
            int idx = (__float_as_int(mt.y) + 8) >> 4;
            gv[q] = __ldg(&g_Gout[(size_t)idx * OO + tid]);
            mm[q] = mt.x;
        }
        #pragma unroll
        for (int q = 0; q < 16; ++q)
            acc = fmaf(0.9f, acc, gv[q] * (0.1f * mm[q]));
    }
    float* op = out + ((size_t)b * SS + t0) * OO + tid;
    for (int jb = 0; jb < 128; jb += 16) {
        float gv[16], mm[16];
        #pragma unroll
        for (int q = 0; q < 16; ++q) {
            float2 mt = smt[nwarm + jb + q];
            int idx = (__float_as_int(mt.y) + 8) >> 4;
            gv[q] = __ldg(&g_Gout[(size_t)idx * OO + tid]);
            mm[q] = mt.x;
        }
        #pragma unroll
        for (int q = 0; q < 16; ++q) {
            acc = fmaf(0.9f, acc, gv[q] * (0.1f * mm[q]));
            op[(jb + q) * OO] = acc + bv;
        }
    }
}

// ---------------- launch ---------------------------------------------------
extern "C" void kernel_launch(void* const* d_in, const int* in_sizes, int n_in,
                              void* d_out, int out_size) {
    const float* x    = (const float*)d_in[0];
    const float* ip   = (const float*)d_in[1];
    const float* ir   = (const float*)d_in[2];
    const float* rp   = (const float*)d_in[3];
    const float* rr   = (const float*)d_in[4];
    const float* W    = (const float*)d_in[5];
    const float* bias = (const float*)d_in[6];
    float* out = (float*)d_out;

    cudaFuncSetAttribute(k_scan,    cudaFuncAttributeMaxDynamicSharedMemorySize, SCAN_SMEM);
    cudaFuncSetAttribute(k_tab_out, cudaFuncAttributeMaxDynamicSharedMemorySize, TOB_SMEM);

    k_dot<<<(BB*SS)/8, 256>>>(x, ir);
    k_tab<<<(N4/256) + 1, 256>>>(rp, ip, rr);
    dim3 tg(33, 4);
    k_tab_out<<<tg, 128, TOB_SMEM>>>(W, rp, ip);
    k_scan<<<BB, 256, SCAN_SMEM>>>();
    k_vo<<<BB*16, 64>>>(out, bias);
}

// round 5
// speedup vs baseline: 9.0021x; 1.2707x over previous
#include <cuda_runtime.h>

#define BB 32
#define SS 2048
#define II 128
#define HH 512
#define OO 64
#define N4 16384            // scan table: tau in [0,4], nearest-neighbor
#define KSC 4096.0f         // N4/4
#define NO 2048             // readout table grid
#define MAGICF 12582912.0f  // 1.5*2^23
#define MAGICI 1262485504   // bits of MAGICF
#define LCH 16
#define NSWEEP 7            // + emission pass = 8 total (0.9^112 ~ 7e-6)

#define DOT_BLKS 256
#define TAB_BLKS 65
#define TOUT_BLKS 128       // 16 k-groups x 8 o-groups
#define PREP_BLKS (DOT_BLKS + TAB_BLKS + TOUT_BLKS)

// ---------------- scratch ----------------
__device__ float  g_dot[BB*SS];
__device__ float2 g_mtau[BB*SS];                    // (m, int_bits(ib))
__device__ __align__(16) float g_G4[N4+260];        // scalar recurrence table
__device__ __align__(16) float g_Gout[NO*OO];       // readout tables

// tau in [0,4) -> diamond direction (S,C), |S|+|C|=1
__device__ __forceinline__ void tau_to_sc(float tau, float& Sv, float& Cv) {
    if (tau >= 4.0f) tau -= 4.0f;
    int q = (int)tau; if (q > 3) q = 3;
    float u = tau - (float)q;
    switch (q) {
        case 0:  Sv = 1.0f - u; Cv = u;        break;
        case 1:  Sv = -u;       Cv = 1.0f - u; break;
        case 2:  Sv = u - 1.0f; Cv = -u;       break;
        default: Sv = u;        Cv = u - 1.0f; break;
    }
}

// one recurrence step; magic-folded rounding, minimal critical chain
__device__ __forceinline__ void scan_step(float c, float& s, const float* __restrict__ tab,
                                          float& m_out, int& ib_out) {
    float ac  = fabsf(c) + 1e-35f;
    float Kac = KSC * ac;
    float Ap, An, BpM;
    if (c >= 0.f) { Ap =  Kac; An = -Kac; BpM = MAGICF; }
    else          { Ap = -Kac; An =  Kac; BpM = MAGICF + 16384.f; }
    float m = fabsf(s) + ac;
    float r; asm("rcp.approx.f32 %0, %1;" : "=f"(r) : "f"(m));
    bool sp = (s >= 0.f);
    float aqs = sp ? Ap  : An;
    float qaK = sp ? BpM : (MAGICF + 8192.f);
    float y  = fmaf(aqs, r, qaK);          // FMA rounds to integer grid (ulp=1)
    int   ib = __float_as_int(y) - MAGICI; // 0..16384
    float g  = tab[ib];
    m_out = m; ib_out = ib;
    s = fmaf(g, 0.1f * m, 0.9f * s);
}

// ---------------- K1: fused prep (dot | scan-table | readout-tables) ------
#define PREP_SMEM ((HH*12 + 32*132 + 2*HH) * 4)   // 45.5 KB
__global__ void __launch_bounds__(256, 4)
k_prep(const float* __restrict__ x,  const float* __restrict__ ir,
       const float* __restrict__ ipv, const float* __restrict__ rp,
       const float* __restrict__ rr, const float* __restrict__ W) {
    extern __shared__ float sm[];
    int bx = blockIdx.x, tid = threadIdx.x;

    if (bx < DOT_BLKS) {
        // ---- role A: dot[b,t] = x[row,:] . ir  (32 rows per warp) ----
        int w = tid >> 5, lane = tid & 31;
        int rbase = bx * 256 + w * 32;
        float4 irv = ((const float4*)ir)[lane];
        #pragma unroll
        for (int i = 0; i < 32; i += 4) {
            float4 a[4];
            #pragma unroll
            for (int q = 0; q < 4; ++q)
                a[q] = ((const float4*)(x + (size_t)(rbase + i + q) * II))[lane];
            #pragma unroll
            for (int q = 0; q < 4; ++q) {
                float p = a[q].x*irv.x + a[q].y*irv.y + a[q].z*irv.z + a[q].w*irv.w;
                #pragma unroll
                for (int o = 16; o; o >>= 1) p += __shfl_xor_sync(0xFFFFFFFFu, p, o);
                if (lane == 0) g_dot[rbase + i + q] = p;
            }
        }
    } else if (bx < DOT_BLKS + TAB_BLKS) {
        // ---- role B: scan table G4[k] ----
        float* srp = sm; float* sip = sm + HH; float* srr = sm + 2*HH;
        for (int h = tid; h < HH; h += 256) { srp[h]=rp[h]; sip[h]=ipv[h]; srr[h]=rr[h]; }
        __syncthreads();
        int k = (bx - DOT_BLKS) * 256 + tid;
        if (k < N4 + 8) {
            float Sv, Cv; tau_to_sc((float)k * (4.0f / N4), Sv, Cv);
            float acc = 0.f;
            #pragma unroll 4
            for (int h = 0; h < HH; ++h)
                acc = fmaf(srr[h], fmaxf(fmaf(Sv, srp[h], Cv * sip[h]), 0.f), acc);
            g_G4[k] = acc;
        }
    } else {
        // ---- role C: readout tables, 128k x 8o per block ----
        float* Wsm = sm;                    // [512][12]
        float* su  = sm + HH * 12;          // [32][132]
        float* srp = su + 32 * 132;         // [512]
        float* sip = srp + HH;              // [512]
        int to = bx - (DOT_BLKS + TAB_BLKS);
        int kg = to >> 3, og = to & 7;
        int k0 = kg * 128, o0 = og * 8;
        if (tid < 128) {
            ((float4*)srp)[tid] = ((const float4*)rp)[tid];
            ((float4*)sip)[tid] = ((const float4*)ipv)[tid];
        }
        {   // stage W o-tile transposed
            int o = tid >> 5, lane = tid & 31;
            const float4* wr = (const float4*)(W + (size_t)(o0 + o) * HH);
            #pragma unroll
            for (int j = 0; j < 4; ++j) {
                float4 wv = wr[lane + j * 32];
                int h = (lane + j * 32) * 4;
                Wsm[(h+0)*12 + o] = wv.x; Wsm[(h+1)*12 + o] = wv.y;
                Wsm[(h+2)*12 + o] = wv.z; Wsm[(h+3)*12 + o] = wv.w;
            }
        }
        __syncthreads();
        int ku = tid & 127, half = tid >> 7;
        float Svu, Cvu; tau_to_sc((float)(k0 + ku) * (4.0f / NO), Svu, Cvu);
        int km = tid >> 1, oq = tid & 1;
        float4 acc = make_float4(0,0,0,0);
        for (int ht = 0; ht < 16; ++ht) {
            int hb = ht * 32;
            #pragma unroll
            for (int hh = half * 16; hh < half * 16 + 16; ++hh)
                su[hh * 132 + ku] = fmaxf(fmaf(Svu, srp[hb+hh], Cvu * sip[hb+hh]), 0.f);
            __syncthreads();
            #pragma unroll 8
            for (int hh = 0; hh < 32; ++hh) {
                float u  = su[hh * 132 + km];
                float4 w = *(const float4*)&Wsm[(hb + hh) * 12 + 4 * oq];
                acc.x = fmaf(u, w.x, acc.x); acc.y = fmaf(u, w.y, acc.y);
                acc.z = fmaf(u, w.z, acc.z); acc.w = fmaf(u, w.w, acc.w);
            }
            __syncthreads();
        }
        ((float4*)(g_Gout + (size_t)(k0 + km) * OO + o0))[oq] = acc;
    }
}

// ---------------- K2: waveform-relaxation scan ----------------------------
#define SCAN_SMEM (((N4 + 8) + SS + 136) * 4)
__global__ void k_scan() {
    extern __shared__ float sm[];
    float* tab    = sm;                        // N4+8
    float* sdot   = sm + (N4 + 8);             // SS
    float* sbound = sdot + SS;                 // 136
    int b = blockIdx.x, tid = threadIdx.x;     // 512 threads
    const float4* g4 = (const float4*)g_G4;
    float4* t4 = (float4*)tab;
    for (int i = tid; i < (N4 + 8) / 4; i += 512) t4[i] = g4[i];
    for (int t = tid; t < SS; t += 512) sdot[t] = g_dot[b * SS + t];
    if (tid < 136) sbound[tid] = 0.f;
    __syncthreads();

    float mo; int ibo;
    for (int sw = 0; sw < NSWEEP; ++sw) {
        float s = (tid < 128) ? sbound[tid] : 0.f;
        __syncthreads();
        if (tid < 128) {
            const float* cd = sdot + tid * LCH;
            #pragma unroll
            for (int j = 0; j < LCH; ++j) scan_step(cd[j], s, tab, mo, ibo);
            sbound[tid + 1] = s;
        }
        __syncthreads();
    }
    // emission pass with converged boundaries
    if (tid < 128) {
        float s = sbound[tid];
        const float* cd = sdot + tid * LCH;
        float2* out = g_mtau + b * SS + tid * LCH;
        #pragma unroll
        for (int j = 0; j < LCH; ++j) {
            scan_step(cd[j], s, tab, mo, ibo);
            out[j] = make_float2(mo, __int_as_float(ibo));
        }
    }
}

// ---------------- K3: fused readout lookup + EMA + bias -------------------
__global__ void k_vo(float* __restrict__ out, const float* __restrict__ bias) {
    __shared__ float2 smt[256];
    int b  = blockIdx.x >> 4;
    int ch = blockIdx.x & 15;
    int t0 = ch * 128;
    int tw = (ch == 0) ? 0 : t0 - 128;
    int nt = t0 + 128 - tw;
    int tid = threadIdx.x;          // 64, one per o
    for (int i = tid; i < nt; i += 64) smt[i] = g_mtau[b * SS + tw + i];
    __syncthreads();
    float bv = bias[tid];
    float acc = 0.f;
    int nwarm = t0 - tw;            // 0 or 128
    for (int jb = 0; jb < nwarm; jb += 16) {
        float gv[16], mm[16];
        #pragma unroll
        for (int q = 0; q < 16; ++q) {
            float2 mt = smt[jb + q];
            int idx = ((__float_as_int(mt.y) + 4) >> 3) & (NO - 1);
            gv[q] = __ldg(&g_Gout[(size_t)idx * OO + tid]);
            mm[q] = mt.x;
        }
        #pragma unroll
        for (int q = 0; q < 16; ++q)
            acc = fmaf(0.9f, acc, gv[q] * (0.1f * mm[q]));
    }
    float* op = out + ((size_t)b * SS + t0) * OO + tid;
    for (int jb = 0; jb < 128; jb += 16) {
        float gv[16], mm[16];
        #pragma unroll
        for (int q = 0; q < 16; ++q) {
            float2 mt = smt[nwarm + jb + q];
            int idx = ((__float_as_int(mt.y) + 4) >> 3) & (NO - 1);
            gv[q] = __ldg(&g_Gout[(size_t)idx * OO + tid]);
            mm[q] = mt.x;
        }
        #pragma unroll
        for (int q = 0; q < 16; ++q) {
            acc = fmaf(0.9f, acc, gv[q] * (0.1f * mm[q]));
            op[(jb + q) * OO] = acc + bv;
        }
    }
}

// ---------------- launch ---------------------------------------------------
extern "C" void kernel_launch(void* const* d_in, const int* in_sizes, int n_in,
                              void* d_out, int out_size) {
    const float* x    = (const float*)d_in[0];
    const float* ip   = (const float*)d_in[1];
    const float* ir   = (const float*)d_in[2];
    const float* rp   = (const float*)d_in[3];
    const float* rr   = (const float*)d_in[4];
    const float* W    = (const float*)d_in[5];
    const float* bias = (const float*)d_in[6];
    float* out = (float*)d_out;

    cudaFuncSetAttribute(k_scan, cudaFuncAttributeMaxDynamicSharedMemorySize, SCAN_SMEM);

    k_prep<<<PREP_BLKS, 256, PREP_SMEM>>>(x, ir, ip, rp, rr, W);
    k_scan<<<BB, 512, SCAN_SMEM>>>();
    k_vo<<<BB*16, 64>>>(out, bias);
}

// round 6
// speedup vs baseline: 9.3643x; 1.0402x over previous
#include <cuda_runtime.h>

#define BB 32
#define SS 2048
#define II 128
#define HH 512
#define OO 64
#define N4 16384            // scan table: tau in [0,4], nearest-neighbor
#define KSC 4096.0f         // N4/4
#define NO 2048             // readout table grid
#define MAGICF 12582912.0f  // 1.5*2^23
#define MAGICI 1262485504   // bits of MAGICF
#define LCH 16
#define NSWEEP 6            // + emission pass = 7 total (0.9^112 ~ 7e-6)

#define DOT_BLKS 256
#define TAB_BLKS 65
#define TOUT_BLKS 128       // 16 k-groups x 8 o-groups
#define PREP_BLKS (DOT_BLKS + TAB_BLKS + TOUT_BLKS)

// ---------------- scratch ----------------
__device__ __align__(16) float  g_dot[BB*SS];
__device__ float2 g_mtau[BB*SS];                    // (m, int_bits(ib))
__device__ __align__(16) float g_G4[N4+260];        // scalar recurrence table
__device__ __align__(16) float g_Gout[NO*OO];       // readout tables

// tau in [0,4) -> diamond direction (S,C), |S|+|C|=1
__device__ __forceinline__ void tau_to_sc(float tau, float& Sv, float& Cv) {
    if (tau >= 4.0f) tau -= 4.0f;
    int q = (int)tau; if (q > 3) q = 3;
    float u = tau - (float)q;
    switch (q) {
        case 0:  Sv = 1.0f - u; Cv = u;        break;
        case 1:  Sv = -u;       Cv = 1.0f - u; break;
        case 2:  Sv = u - 1.0f; Cv = -u;       break;
        default: Sv = u;        Cv = u - 1.0f; break;
    }
}

// one recurrence step; magic-folded rounding, minimal critical chain
__device__ __forceinline__ void scan_step(float c, float& s, const float* __restrict__ tab,
                                          float& m_out, int& ib_out) {
    float ac  = fabsf(c) + 1e-35f;
    float Kac = KSC * ac;
    float Ap, An, BpM;
    if (c >= 0.f) { Ap =  Kac; An = -Kac; BpM = MAGICF; }
    else          { Ap = -Kac; An =  Kac; BpM = MAGICF + 16384.f; }
    float m = fabsf(s) + ac;
    float r; asm("rcp.approx.f32 %0, %1;" : "=f"(r) : "f"(m));
    bool sp = (s >= 0.f);
    float aqs = sp ? Ap  : An;
    float qaK = sp ? BpM : (MAGICF + 8192.f);
    float y  = fmaf(aqs, r, qaK);          // FMA rounds to integer grid (ulp=1)
    int   ib = __float_as_int(y) - MAGICI; // 0..16384
    float g  = tab[ib];
    m_out = m; ib_out = ib;
    s = fmaf(g, 0.1f * m, 0.9f * s);
}

// ---------------- K1: fused prep (dot | scan-table | readout-tables) ------
#define PREP_SMEM ((HH*12 + 32*132 + 2*HH) * 4)   // 45.5 KB
__global__ void __launch_bounds__(256)
k_prep(const float* __restrict__ x,  const float* __restrict__ ir,
       const float* __restrict__ ipv, const float* __restrict__ rp,
       const float* __restrict__ rr, const float* __restrict__ W) {
    extern __shared__ float sm[];
    int bx = blockIdx.x, tid = threadIdx.x;

    if (bx < DOT_BLKS) {
        // ---- role A: dot[row] = x[row,:] . ir  (32 rows/warp, 8-row batches) ----
        int w = tid >> 5, lane = tid & 31;
        int rbase = bx * 256 + w * 32;
        float4 irv = ((const float4*)ir)[lane];
        #pragma unroll
        for (int i = 0; i < 32; i += 8) {
            float4 a[8];
            #pragma unroll
            for (int q = 0; q < 8; ++q)
                a[q] = ((const float4*)(x + (size_t)(rbase + i + q) * II))[lane];
            float p[8];
            #pragma unroll
            for (int q = 0; q < 8; ++q)
                p[q] = a[q].x*irv.x + a[q].y*irv.y + a[q].z*irv.z + a[q].w*irv.w;
            #pragma unroll
            for (int o = 16; o; o >>= 1) {
                #pragma unroll
                for (int q = 0; q < 8; ++q)
                    p[q] += __shfl_xor_sync(0xFFFFFFFFu, p[q], o);
            }
            if (lane == 0) {
                ((float4*)(g_dot + rbase + i))[0] = make_float4(p[0], p[1], p[2], p[3]);
                ((float4*)(g_dot + rbase + i))[1] = make_float4(p[4], p[5], p[6], p[7]);
            }
        }
    } else if (bx < DOT_BLKS + TAB_BLKS) {
        // ---- role B: scan table G4[k] ----
        float* srp = sm; float* sip = sm + HH; float* srr = sm + 2*HH;
        for (int h = tid; h < HH; h += 256) { srp[h]=rp[h]; sip[h]=ipv[h]; srr[h]=rr[h]; }
        __syncthreads();
        int k = (bx - DOT_BLKS) * 256 + tid;
        if (k < N4 + 8) {
            float Sv, Cv; tau_to_sc((float)k * (4.0f / N4), Sv, Cv);
            float acc = 0.f;
            #pragma unroll 4
            for (int h = 0; h < HH; ++h)
                acc = fmaf(srr[h], fmaxf(fmaf(Sv, srp[h], Cv * sip[h]), 0.f), acc);
            g_G4[k] = acc;
        }
    } else {
        // ---- role C: readout tables, 128k x 8o per block ----
        float* Wsm = sm;                    // [512][12]
        float* su  = sm + HH * 12;          // [32][132]
        float* srp = su + 32 * 132;         // [512]
        float* sip = srp + HH;              // [512]
        int to = bx - (DOT_BLKS + TAB_BLKS);
        int kg = to >> 3, og = to & 7;
        int k0 = kg * 128, o0 = og * 8;
        if (tid < 128) {
            ((float4*)srp)[tid] = ((const float4*)rp)[tid];
            ((float4*)sip)[tid] = ((const float4*)ipv)[tid];
        }
        {   // stage W o-tile transposed
            int o = tid >> 5, lane = tid & 31;
            const float4* wr = (const float4*)(W + (size_t)(o0 + o) * HH);
            #pragma unroll
            for (int j = 0; j < 4; ++j) {
                float4 wv = wr[lane + j * 32];
                int h = (lane + j * 32) * 4;
                Wsm[(h+0)*12 + o] = wv.x; Wsm[(h+1)*12 + o] = wv.y;
                Wsm[(h+2)*12 + o] = wv.z; Wsm[(h+3)*12 + o] = wv.w;
            }
        }
        __syncthreads();
        int ku = tid & 127, half = tid >> 7;
        float Svu, Cvu; tau_to_sc((float)(k0 + ku) * (4.0f / NO), Svu, Cvu);
        int km = tid >> 1, oq = tid & 1;
        float4 acc = make_float4(0,0,0,0);
        for (int ht = 0; ht < 16; ++ht) {
            int hb = ht * 32;
            #pragma unroll
            for (int hh = half * 16; hh < half * 16 + 16; ++hh)
                su[hh * 132 + ku] = fmaxf(fmaf(Svu, srp[hb+hh], Cvu * sip[hb+hh]), 0.f);
            __syncthreads();
            #pragma unroll 8
            for (int hh = 0; hh < 32; ++hh) {
                float u  = su[hh * 132 + km];
                float4 w = *(const float4*)&Wsm[(hb + hh) * 12 + 4 * oq];
                acc.x = fmaf(u, w.x, acc.x); acc.y = fmaf(u, w.y, acc.y);
                acc.z = fmaf(u, w.z, acc.z); acc.w = fmaf(u, w.w, acc.w);
            }
            __syncthreads();
        }
        ((float4*)(g_Gout + (size_t)(k0 + km) * OO + o0))[oq] = acc;
    }
}

// ---------------- K2: waveform-relaxation scan ----------------------------
#define SCAN_SMEM (((N4 + 8) + SS + 136) * 4)
__global__ void k_scan() {
    extern __shared__ float sm[];
    float* tab    = sm;                        // N4+8
    float* sdot   = sm + (N4 + 8);             // SS
    float* sbound = sdot + SS;                 // 136
    int b = blockIdx.x, tid = threadIdx.x;     // 512 threads
    const float4* g4 = (const float4*)g_G4;
    float4* t4 = (float4*)tab;
    for (int i = tid; i < (N4 + 8) / 4; i += 512) t4[i] = g4[i];
    if (tid < 512) {
        ((float4*)sdot)[tid] = ((const float4*)(g_dot + b * SS))[tid];
    }
    if (tid < 136) sbound[tid] = 0.f;
    __syncthreads();

    float mo; int ibo;
    for (int sw = 0; sw < NSWEEP; ++sw) {
        float s = (tid < 128) ? sbound[tid] : 0.f;
        __syncthreads();
        if (tid < 128) {
            const float* cd = sdot + tid * LCH;
            #pragma unroll
            for (int j = 0; j < LCH; ++j) scan_step(cd[j], s, tab, mo, ibo);
            sbound[tid + 1] = s;
        }
        __syncthreads();
    }
    // emission pass with converged boundaries
    if (tid < 128) {
        float s = sbound[tid];
        const float* cd = sdot + tid * LCH;
        float2* out = g_mtau + b * SS + tid * LCH;
        #pragma unroll
        for (int j = 0; j < LCH; ++j) {
            scan_step(cd[j], s, tab, mo, ibo);
            out[j] = make_float2(mo, __int_as_float(ibo));
        }
    }
}

// ---------------- K3: fused readout lookup + EMA + bias -------------------
__global__ void k_vo(float* __restrict__ out, const float* __restrict__ bias) {
    __shared__ float2 smt[256];
    int b  = blockIdx.x >> 4;
    int ch = blockIdx.x & 15;
    int t0 = ch * 128;
    int tw = (ch == 0) ? 0 : t0 - 128;
    int nt = t0 + 128 - tw;
    int tid = threadIdx.x;          // 64, one per o
    for (int i = tid; i < nt; i += 64) smt[i] = g_mtau[b * SS + tw + i];
    __syncthreads();
    float bv = bias[tid];
    float acc = 0.f;
    int nwarm = t0 - tw;            // 0 or 128
    for (int jb = 0; jb < nwarm; jb += 16) {
        float gv[16], mm[16];
        #pragma unroll
        for (int q = 0; q < 16; ++q) {
            float2 mt = smt[jb + q];
            int idx = ((__float_as_int(mt.y) + 4) >> 3) & (NO - 1);
            gv[q] = __ldg(&g_Gout[(size_t)idx * OO + tid]);
            mm[q] = mt.x;
        }
        #pragma unroll
        for (int q = 0; q < 16; ++q)
            acc = fmaf(0.9f, acc, gv[q] * (0.1f * mm[q]));
    }
    float* op = out + ((size_t)b * SS + t0) * OO + tid;
    for (int jb = 0; jb < 128; jb += 16) {
        float gv[16], mm[16];
        #pragma unroll
        for (int q = 0; q < 16; ++q) {
            float2 mt = smt[nwarm + jb + q];
            int idx = ((__float_as_int(mt.y) + 4) >> 3) & (NO - 1);
            gv[q] = __ldg(&g_Gout[(size_t)idx * OO + tid]);
            mm[q] = mt.x;
        }
        #pragma unroll
        for (int q = 0; q < 16; ++q) {
            acc = fmaf(0.9f, acc, gv[q] * (0.1f * mm[q]));
            op[(jb + q) * OO] = acc + bv;
        }
    }
}

// ---------------- launch ---------------------------------------------------
extern "C" void kernel_launch(void* const* d_in, const int* in_sizes, int n_in,
                              void* d_out, int out_size) {
    const float* x    = (const float*)d_in[0];
    const float* ip   = (const float*)d_in[1];
    const float* ir   = (const float*)d_in[2];
    const float* rp   = (const float*)d_in[3];
    const float* rr   = (const float*)d_in[4];
    const float* W    = (const float*)d_in[5];
    const float* bias = (const float*)d_in[6];
    float* out = (float*)d_out;

    cudaFuncSetAttribute(k_scan, cudaFuncAttributeMaxDynamicSharedMemorySize, SCAN_SMEM);

    k_prep<<<PREP_BLKS, 256, PREP_SMEM>>>(x, ir, ip, rp, rr, W);
    k_scan<<<BB, 512, SCAN_SMEM>>>();
    k_vo<<<BB*16, 64>>>(out, bias);
}